// round 7
// baseline (speedup 1.0000x reference)
#include <cuda_runtime.h>
#include <cuda_bf16.h>
#include <cstdint>
#include <cstddef>

// ---------------------------------------------------------------------------
// Problem constants
// ---------------------------------------------------------------------------
namespace {
constexpr int Hc    = 128;
constexpr int NRFc  = 16;
constexpr int NUSER = 4096;
constexpr int NAG   = 16384;
constexpr int APAD  = 136;        // bf16 elems per smem row
constexpr int ASTR  = APAD * 2;   // 272 bytes
constexpr int T64   = 64  * ASTR; // 17408
constexpr int T128  = 128 * ASTR; // 34816
constexpr int NTG   = 128;        // GEMM kernel threads (4 warps)
constexpr int NTK1  = 512;
constexpr int SM_G  = 2 * T64 + 2 * T128;   // 104448 -> 2 CTAs/SM
}

// ---------------------------------------------------------------------------
// Scratch (device globals — no allocation allowed)
// ---------------------------------------------------------------------------
__device__ float g_hu    [NUSER * Hc];
__device__ float g_ha2   [NAG   * Hc];
__device__ float g_meanA [256 * Hc];
__device__ float g_meanU [256 * Hc];
__device__ float g_meanA2[256 * Hc];
__device__ float g_hag   [256 * Hc];
// Pre-transposed + hi/lo-split weights: slots 0..5 = HxH, slot 6 = W_norm' (64x128)
__device__ __nv_bfloat16 g_wt_hi[7 * Hc * Hc];
__device__ __nv_bfloat16 g_wt_lo[7 * Hc * Hc];

// ---------------------------------------------------------------------------
// Helpers
// ---------------------------------------------------------------------------
__device__ __forceinline__ uint32_t smem_u32(const void* p) {
    uint32_t a;
    asm("{ .reg .u64 t; cvta.to.shared.u64 t, %1; cvt.u32.u64 %0, t; }"
        : "=r"(a) : "l"(p));
    return a;
}
__device__ __forceinline__ void ldsm4(uint32_t* r, uint32_t addr) {
    asm volatile("ldmatrix.sync.aligned.m8n8.x4.shared.b16 {%0,%1,%2,%3}, [%4];"
                 : "=r"(r[0]), "=r"(r[1]), "=r"(r[2]), "=r"(r[3]) : "r"(addr));
}
__device__ __forceinline__ void mma16816(float* d, const uint32_t* a, const uint32_t* b) {
    asm volatile(
        "mma.sync.aligned.m16n8k16.row.col.f32.bf16.bf16.f32 "
        "{%0,%1,%2,%3}, {%4,%5,%6,%7}, {%8,%9}, {%0,%1,%2,%3};"
        : "+f"(d[0]), "+f"(d[1]), "+f"(d[2]), "+f"(d[3])
        : "r"(a[0]), "r"(a[1]), "r"(a[2]), "r"(a[3]), "r"(b[0]), "r"(b[1]));
}
__device__ __forceinline__ uint32_t pack_bf2(__nv_bfloat16 a, __nv_bfloat16 b) {
    return (uint32_t)__bfloat16_as_ushort(a) | ((uint32_t)__bfloat16_as_ushort(b) << 16);
}
__device__ __forceinline__ void split2(float a, float b, uint32_t& hi, uint32_t& lo) {
    const __nv_bfloat16 h0 = __float2bfloat16(a), h1 = __float2bfloat16(b);
    hi = pack_bf2(h0, h1);
    lo = pack_bf2(__float2bfloat16(a - __bfloat162float(h0)),
                  __float2bfloat16(b - __bfloat162float(h1)));
}

// plain-LDG B tile load (pre-split weights) into padded smem
__device__ __forceinline__ void load_B_sync(const __nv_bfloat16* __restrict__ Wh,
                                            const __nv_bfloat16* __restrict__ Wl,
                                            char* pBh, char* pBl, int tid, int rows)
{
    const uint4* wh = reinterpret_cast<const uint4*>(Wh);
    const uint4* wl = reinterpret_cast<const uint4*>(Wl);
    for (int i = tid; i < rows * 16; i += NTG) {
        const uint32_t o = (uint32_t)((i >> 4) * ASTR + (i & 15) * 16);
        *reinterpret_cast<uint4*>(pBh + o) = wh[i];
        *reinterpret_cast<uint4*>(pBl + o) = wl[i];
    }
}

// A tile (TM=64): fp32 load (+optional group-broadcast add), hi/lo split
template<int SHIFT>
__device__ __forceinline__ void load_split_A(const float* __restrict__ A,
                                             const float* __restrict__ addv,
                                             int row0, char* pAh, char* pAl, int tid)
{
    for (int i = tid; i < 64 * 16; i += NTG) {
        const int r = i >> 4, k = (i & 15) * 8;
        const float* ap = A + (size_t)(row0 + r) * Hc + k;
        float v[8];
        *reinterpret_cast<float4*>(&v[0]) = *reinterpret_cast<const float4*>(ap);
        *reinterpret_cast<float4*>(&v[4]) = *reinterpret_cast<const float4*>(ap + 4);
        if (addv) {
            const float* mp = addv + ((row0 + r) >> SHIFT) * Hc + k;
            float m[8];
            *reinterpret_cast<float4*>(&m[0]) = *reinterpret_cast<const float4*>(mp);
            *reinterpret_cast<float4*>(&m[4]) = *reinterpret_cast<const float4*>(mp + 4);
            #pragma unroll
            for (int j = 0; j < 8; ++j) v[j] += m[j];
        }
        uint32_t hb[4], lb[4];
        #pragma unroll
        for (int j = 0; j < 4; ++j) split2(v[2*j], v[2*j+1], hb[j], lb[j]);
        const uint32_t o = (uint32_t)(r * ASTR + (i & 15) * 16);
        *reinterpret_cast<uint4*>(pAh + o) = *reinterpret_cast<uint4*>(hb);
        *reinterpret_cast<uint4*>(pAl + o) = *reinterpret_cast<uint4*>(lb);
    }
}

// 3-pass hi/lo MMA over K=128 (R4-proven inner loop). Warp tile 32 x (NF*8).
template<int MF, int NF>
__device__ __forceinline__ void mma_3p(uint32_t aAh, uint32_t aAl,
                                       uint32_t aBh, uint32_t aBl,
                                       uint32_t a_off, uint32_t b_off,
                                       float (*acc)[NF][4])
{
    #pragma unroll
    for (int pass = 0; pass < 3; ++pass) {
        const uint32_t Ab = (pass == 2 ? aAl : aAh) + a_off;
        const uint32_t Bb = (pass == 1 ? aBl : aBh) + b_off;
        #pragma unroll
        for (int kc = 0; kc < 8; ++kc) {
            const uint32_t kb = (uint32_t)kc * 32;
            uint32_t af[MF][4];
            #pragma unroll
            for (int mf = 0; mf < MF; ++mf)
                ldsm4(af[mf], Ab + (uint32_t)(mf * 16 * ASTR) + kb);
            uint32_t bfr[NF][2];
            #pragma unroll
            for (int p = 0; p < NF / 2; ++p) {
                uint32_t t[4];
                ldsm4(t, Bb + (uint32_t)(p * 16 * ASTR) + kb);
                bfr[2*p][0] = t[0]; bfr[2*p][1] = t[1];
                bfr[2*p+1][0] = t[2]; bfr[2*p+1][1] = t[3];
            }
            #pragma unroll
            for (int mf = 0; mf < MF; ++mf)
                #pragma unroll
                for (int nf = 0; nf < NF; ++nf)
                    mma16816(acc[mf][nf], af[mf], bfr[nf]);
        }
    }
}
template<int MF, int NF>
__device__ __forceinline__ void zero_acc(float (*acc)[NF][4]) {
    #pragma unroll
    for (int mf = 0; mf < MF; ++mf)
        #pragma unroll
        for (int nf = 0; nf < NF; ++nf)
            acc[mf][nf][0] = acc[mf][nf][1] = acc[mf][nf][2] = acc[mf][nf][3] = 0.f;
}

// epilogue: relu(acc+b) (+mean[g]) re-split into A tiles
template<int MF, int NF, bool ADDMEAN, int SHIFT>
__device__ __forceinline__ void epi_resplit(float (*acc)[NF][4],
                                            const float* __restrict__ bias,
                                            const float* __restrict__ meanv,
                                            char* pAh, char* pAl,
                                            int row0, int m0, int n0, int lane)
{
    const int tq = lane & 3, gq = lane >> 2;
    #pragma unroll
    for (int mf = 0; mf < MF; ++mf) {
        const int r0 = m0 + mf * 16 + gq;
        const int g = ADDMEAN ? ((SHIFT == 6) ? ((row0 + m0) >> 6)
                                              : ((row0 + m0 + mf * 16) >> 4)) : 0;
        #pragma unroll
        for (int nf = 0; nf < NF; ++nf) {
            const int c = n0 + nf * 8 + 2 * tq;
            float mx = 0.f, my = 0.f;
            if (ADDMEAN) {
                const float2 mv = *reinterpret_cast<const float2*>(&meanv[g * Hc + c]);
                mx = mv.x; my = mv.y;
            }
            const float bb0 = bias[c], bb1 = bias[c + 1];
            const float e0 = fmaxf(acc[mf][nf][0] + bb0, 0.f) + mx;
            const float e1 = fmaxf(acc[mf][nf][1] + bb1, 0.f) + my;
            const float e2 = fmaxf(acc[mf][nf][2] + bb0, 0.f) + mx;
            const float e3 = fmaxf(acc[mf][nf][3] + bb1, 0.f) + my;
            uint32_t hi0, lo0, hi1, lo1;
            split2(e0, e1, hi0, lo0);
            split2(e2, e3, hi1, lo1);
            *reinterpret_cast<uint32_t*>(pAh + r0 * ASTR + c * 2) = hi0;
            *reinterpret_cast<uint32_t*>(pAl + r0 * ASTR + c * 2) = lo0;
            *reinterpret_cast<uint32_t*>(pAh + (r0 + 8) * ASTR + c * 2) = hi1;
            *reinterpret_cast<uint32_t*>(pAl + (r0 + 8) * ASTR + c * 2) = lo1;
        }
    }
}

// mean-16 epilogue: each 16-row m-frag is one group
template<int MF, int NF>
__device__ __forceinline__ void epi_mean16(float (*acc)[NF][4],
                                           const float* __restrict__ bias,
                                           float* __restrict__ outp,
                                           int row0, int m0, int n0, int lane)
{
    const int tq = lane & 3;
    #pragma unroll
    for (int mf = 0; mf < MF; ++mf) {
        const int grp = (row0 + m0 + mf * 16) >> 4;
        #pragma unroll
        for (int nf = 0; nf < NF; ++nf) {
            const int c = n0 + nf * 8 + 2 * tq;
            const float bb0 = bias[c], bb1 = bias[c + 1];
            float s0 = fmaxf(acc[mf][nf][0] + bb0, 0.f)
                     + fmaxf(acc[mf][nf][2] + bb0, 0.f);
            float s1 = fmaxf(acc[mf][nf][1] + bb1, 0.f)
                     + fmaxf(acc[mf][nf][3] + bb1, 0.f);
            s0 += __shfl_xor_sync(~0u, s0, 4);  s1 += __shfl_xor_sync(~0u, s1, 4);
            s0 += __shfl_xor_sync(~0u, s0, 8);  s1 += __shfl_xor_sync(~0u, s1, 8);
            s0 += __shfl_xor_sync(~0u, s0, 16); s1 += __shfl_xor_sync(~0u, s1, 16);
            if (lane < 4) {
                float2 o2 = {s0 * 0.0625f, s1 * 0.0625f};
                *reinterpret_cast<float2*>(&outp[grp * Hc + n0 + nf * 8 + 2 * lane]) = o2;
            }
        }
    }
}

// ---------------------------------------------------------------------------
// K1: prep (blocks 0..6) + stage1 (blocks 7..38)   [512 threads] — from R6
// ---------------------------------------------------------------------------
__global__ __launch_bounds__(NTK1, 1)
void k1_prep_stage1(const float* W0, const float* W1, const float* W2,
                    const float* W3, const float* W4, const float* W5,
                    const float* Wn,
                    __nv_bfloat16* oh, __nv_bfloat16* ol,
                    const float* __restrict__ uf,
                    const float* __restrict__ W_ue, const float* __restrict__ b_ue,
                    const float* __restrict__ W_t,  const float* __restrict__ b_t,
                    float* __restrict__ hu, float* __restrict__ hag)
{
    extern __shared__ char smraw[];
    const int tid = threadIdx.x;

    if (blockIdx.x < 7) {
        float* st = reinterpret_cast<float*>(smraw);
        const int m = blockIdx.x;
        uint32_t* ph = reinterpret_cast<uint32_t*>(oh + (size_t)m * Hc * Hc);
        uint32_t* pl = reinterpret_cast<uint32_t*>(ol + (size_t)m * Hc * Hc);
        if (m < 6) {
            const float* Ws[6] = {W0, W1, W2, W3, W4, W5};
            const float* W = Ws[m];
            for (int i = tid; i < Hc * 32; i += NTK1) {
                const int kr = i >> 5, c4 = i & 31;
                *reinterpret_cast<float4*>(&st[kr * 132 + c4 * 4]) =
                    reinterpret_cast<const float4*>(W)[i];
            }
            __syncthreads();
            for (int i = tid; i < Hc * 64; i += NTK1) {
                const int n = i >> 6, k2 = (i & 63) * 2;
                uint32_t hi, lo;
                split2(st[k2 * 132 + n], st[(k2 + 1) * 132 + n], hi, lo);
                ph[n * 64 + (i & 63)] = hi;
                pl[n * 64 + (i & 63)] = lo;
            }
        } else {
            for (int i = tid; i < Hc * 8; i += NTK1) {
                const int kr = i >> 3, c4 = i & 7;
                *reinterpret_cast<float4*>(&st[kr * 36 + c4 * 4]) =
                    reinterpret_cast<const float4*>(Wn)[i];
            }
            __syncthreads();
            for (int i = tid; i < 64 * 64; i += NTK1) {
                const int rowp = i >> 6, k = (i & 63) * 2;
                uint32_t hi = 0, lo = 0;
                if (rowp < 32) {
                    const int n = (rowp & 1) * 16 + (rowp >> 1);
                    split2(st[k * 36 + n], st[(k + 1) * 36 + n], hi, lo);
                }
                ph[rowp * 64 + (i & 63)] = hi;
                pl[rowp * 64 + (i & 63)] = lo;
            }
        }
        return;
    }

    // ---- stage1 ----
    float* sA    = reinterpret_cast<float*>(smraw);           // [128][36]
    float* sW    = reinterpret_cast<float*>(smraw + 18432);   // [32][128]
    float* spart = reinterpret_cast<float*>(smraw + 65536);   // [16][132]
    float* smean = reinterpret_cast<float*>(smraw + 73984);   // [8][132]
    float* sWt   = reinterpret_cast<float*>(smraw);           // phase2: [128][128]

    const int row0 = (blockIdx.x - 7) * 128;

    for (int i = tid; i < 1024; i += NTK1) {
        const int r = i >> 3, k4 = i & 7;
        *reinterpret_cast<float4*>(&sA[r * 36 + k4 * 4]) =
            reinterpret_cast<const float4*>(uf)[(size_t)row0 * 8 + i];
    }
    for (int i = tid; i < 1024; i += NTK1)
        reinterpret_cast<float4*>(sW)[i] = reinterpret_cast<const float4*>(W_ue)[i];
    __syncthreads();

    {
        const int tx = tid & 31, ty = tid >> 5;
        const float4 b4 = reinterpret_cast<const float4*>(b_ue)[tx];
        float4 msum = {0.f, 0.f, 0.f, 0.f};
        #pragma unroll 2
        for (int i = 0; i < 8; ++i) {
            const int r = ty * 8 + i;
            float4 acc = b4;
            #pragma unroll
            for (int k = 0; k < 32; ++k) {
                const float a = sA[r * 36 + k];
                const float4 w = reinterpret_cast<const float4*>(sW)[k * 32 + tx];
                acc.x += a * w.x; acc.y += a * w.y; acc.z += a * w.z; acc.w += a * w.w;
            }
            acc.x = fmaxf(acc.x, 0.f); acc.y = fmaxf(acc.y, 0.f);
            acc.z = fmaxf(acc.z, 0.f); acc.w = fmaxf(acc.w, 0.f);
            reinterpret_cast<float4*>(hu)[(size_t)(row0 + r) * 32 + tx] = acc;
            msum.x += acc.x; msum.y += acc.y; msum.z += acc.z; msum.w += acc.w;
        }
        *reinterpret_cast<float4*>(&spart[ty * 132 + tx * 4]) = msum;
    }
    __syncthreads();
    for (int i = tid; i < 1024; i += NTK1) {
        const int g = i >> 7, c = i & 127;
        smean[g * 132 + c] = (spart[(2*g) * 132 + c] + spart[(2*g+1) * 132 + c]) * 0.0625f;
    }
    __syncthreads();
    for (int i = tid; i < 4096; i += NTK1)
        reinterpret_cast<float4*>(sWt)[i] = reinterpret_cast<const float4*>(W_t)[i];
    __syncthreads();
    if (tid < 256) {
        const int gr = tid >> 5, col4 = tid & 31;
        float4 acc = reinterpret_cast<const float4*>(b_t)[col4];
        #pragma unroll 4
        for (int k = 0; k < 128; ++k) {
            const float a = smean[gr * 132 + k];
            const float4 w = reinterpret_cast<const float4*>(sWt)[k * 32 + col4];
            acc.x += a * w.x; acc.y += a * w.y; acc.z += a * w.z; acc.w += a * w.w;
        }
        acc.x = fmaxf(acc.x, 0.f); acc.y = fmaxf(acc.y, 0.f);
        acc.z = fmaxf(acc.z, 0.f); acc.w = fmaxf(acc.w, 0.f);
        reinterpret_cast<float4*>(hag)[(size_t)((blockIdx.x - 7) * 8 + gr) * 32 + col4] = acc;
    }
}

// ---------------------------------------------------------------------------
// aggr16 (TM=64, grid 64): meanA = mean16(relu(hu @ W0 + b0))
// ---------------------------------------------------------------------------
__global__ __launch_bounds__(NTG, 2)
void gemm_aggr16(const float* __restrict__ A,
                 const __nv_bfloat16* __restrict__ Wh, const __nv_bfloat16* __restrict__ Wl,
                 const float* __restrict__ bias, float* __restrict__ outp)
{
    extern __shared__ char sm[];
    char* pAh = sm;            char* pAl = sm + T64;
    char* pBh = sm + 2 * T64;  char* pBl = pBh + T128;
    const int tid = threadIdx.x;
    const int row0 = blockIdx.x * 64;
    const uint32_t base = smem_u32(sm);

    load_B_sync(Wh, Wl, pBh, pBl, tid, 128);
    load_split_A<0>(A, nullptr, row0, pAh, pAl, tid);
    __syncthreads();

    const int w = tid >> 5, lane = tid & 31;
    const int m0 = (w >> 1) * 32, n0 = (w & 1) * 64;
    const int rr = lane & 7, quad = lane >> 3;
    const uint32_t a_off = (uint32_t)((m0 + rr + ((quad & 1) << 3)) * ASTR + ((quad & 2) << 3));
    const uint32_t b_off = (uint32_t)((n0 + rr + ((quad >> 1) << 3)) * ASTR + ((quad & 1) << 4));

    float acc[2][8][4];
    zero_acc<2, 8>(acc);
    mma_3p<2, 8>(base, base + T64, base + 2 * T64, base + 2 * T64 + T128, a_off, b_off, acc);
    epi_mean16<2, 8>(acc, bias, outp, row0, m0, n0, lane);
}

// ---------------------------------------------------------------------------
// aggr64 (TM=64, grid 256): meanU[blk] = mean64(relu((noise+hag[g]) @ W3 + b3))
// ---------------------------------------------------------------------------
__global__ __launch_bounds__(NTG, 2)
void gemm_aggr64(const float* __restrict__ noise, const float* __restrict__ hag,
                 const __nv_bfloat16* __restrict__ Wh, const __nv_bfloat16* __restrict__ Wl,
                 const float* __restrict__ bias, float* __restrict__ meanU)
{
    extern __shared__ char sm[];
    __shared__ float spart[4][64];
    char* pAh = sm;            char* pAl = sm + T64;
    char* pBh = sm + 2 * T64;  char* pBl = pBh + T128;
    const int tid = threadIdx.x;
    const int row0 = blockIdx.x * 64;
    const uint32_t base = smem_u32(sm);

    load_B_sync(Wh, Wl, pBh, pBl, tid, 128);
    load_split_A<6>(noise, hag, row0, pAh, pAl, tid);
    __syncthreads();

    const int w = tid >> 5, lane = tid & 31;
    const int m0 = (w >> 1) * 32, n0 = (w & 1) * 64;
    const int rr = lane & 7, quad = lane >> 3;
    const uint32_t a_off = (uint32_t)((m0 + rr + ((quad & 1) << 3)) * ASTR + ((quad & 2) << 3));
    const uint32_t b_off = (uint32_t)((n0 + rr + ((quad >> 1) << 3)) * ASTR + ((quad & 1) << 4));

    float acc[2][8][4];
    zero_acc<2, 8>(acc);
    mma_3p<2, 8>(base, base + T64, base + 2 * T64, base + 2 * T64 + T128, a_off, b_off, acc);

    // per-warp column sums over its 32 rows
    const int tq = lane & 3;
    #pragma unroll
    for (int nf = 0; nf < 8; ++nf) {
        const int c = n0 + nf * 8 + 2 * tq;
        const float bb0 = bias[c], bb1 = bias[c + 1];
        float s0 = 0.f, s1 = 0.f;
        #pragma unroll
        for (int mf = 0; mf < 2; ++mf) {
            s0 += fmaxf(acc[mf][nf][0] + bb0, 0.f) + fmaxf(acc[mf][nf][2] + bb0, 0.f);
            s1 += fmaxf(acc[mf][nf][1] + bb1, 0.f) + fmaxf(acc[mf][nf][3] + bb1, 0.f);
        }
        s0 += __shfl_xor_sync(~0u, s0, 4);  s1 += __shfl_xor_sync(~0u, s1, 4);
        s0 += __shfl_xor_sync(~0u, s0, 8);  s1 += __shfl_xor_sync(~0u, s1, 8);
        s0 += __shfl_xor_sync(~0u, s0, 16); s1 += __shfl_xor_sync(~0u, s1, 16);
        if (lane < 4) {
            spart[w][nf * 8 + 2 * lane]     = s0;
            spart[w][nf * 8 + 2 * lane + 1] = s1;
        }
    }
    __syncthreads();
    // combine the two M-warps per column half; c in [0,128)
    {
        const int c = tid;
        const int wnc = c >> 6, ci = c & 63;
        const float tot = spart[wnc][ci] + spart[2 + wnc][ci];
        meanU[blockIdx.x * Hc + c] = tot * (1.0f / 64.0f);
    }
}

// ---------------------------------------------------------------------------
// dual agent (TM=64, grid 256): ha2 = relu((relu((noise+hag)@W1+b1)+meanA[g64])@W2+b2)
// ---------------------------------------------------------------------------
__global__ __launch_bounds__(NTG, 2)
void gemm_dual_agent(const float* __restrict__ noise, const float* __restrict__ hag,
                     const __nv_bfloat16* W1h, const __nv_bfloat16* W1l, const float* b1,
                     const float* __restrict__ meanv,
                     const __nv_bfloat16* W2h, const __nv_bfloat16* W2l, const float* b2,
                     float* __restrict__ outp)
{
    extern __shared__ char sm[];
    char* pAh = sm;            char* pAl = sm + T64;
    char* pBh = sm + 2 * T64;  char* pBl = pBh + T128;
    const int tid = threadIdx.x;
    const int row0 = blockIdx.x * 64;
    const uint32_t base = smem_u32(sm);

    load_B_sync(W1h, W1l, pBh, pBl, tid, 128);
    load_split_A<6>(noise, hag, row0, pAh, pAl, tid);
    __syncthreads();

    const int w = tid >> 5, lane = tid & 31;
    const int m0 = (w >> 1) * 32, n0 = (w & 1) * 64;
    const int rr = lane & 7, quad = lane >> 3;
    const uint32_t a_off = (uint32_t)((m0 + rr + ((quad & 1) << 3)) * ASTR + ((quad & 2) << 3));
    const uint32_t b_off = (uint32_t)((n0 + rr + ((quad >> 1) << 3)) * ASTR + ((quad & 1) << 4));

    float acc[2][8][4];
    zero_acc<2, 8>(acc);
    mma_3p<2, 8>(base, base + T64, base + 2 * T64, base + 2 * T64 + T128, a_off, b_off, acc);
    __syncthreads();
    epi_resplit<2, 8, true, 6>(acc, b1, meanv, pAh, pAl, row0, m0, n0, lane);
    load_B_sync(W2h, W2l, pBh, pBl, tid, 128);
    __syncthreads();
    zero_acc<2, 8>(acc);
    mma_3p<2, 8>(base, base + T64, base + 2 * T64, base + 2 * T64 + T128, a_off, b_off, acc);

    const int tq = lane & 3, gq = lane >> 2;
    #pragma unroll
    for (int mf = 0; mf < 2; ++mf) {
        const int row = row0 + m0 + mf * 16 + gq;
        #pragma unroll
        for (int nf = 0; nf < 8; ++nf) {
            const int c = n0 + nf * 8 + 2 * tq;
            const float bb0 = b2[c], bb1 = b2[c + 1];
            float2 lo = {fmaxf(acc[mf][nf][0] + bb0, 0.f),
                         fmaxf(acc[mf][nf][1] + bb1, 0.f)};
            float2 hi = {fmaxf(acc[mf][nf][2] + bb0, 0.f),
                         fmaxf(acc[mf][nf][3] + bb1, 0.f)};
            *reinterpret_cast<float2*>(&outp[(size_t)row * Hc + c]) = lo;
            *reinterpret_cast<float2*>(&outp[(size_t)(row + 8) * Hc + c]) = hi;
        }
    }
}

// ---------------------------------------------------------------------------
// user triple (TM=64, grid 64): meanA2 = mean16(relu(
//    relu((relu(hu@W4+b4)+meanU[g16])@W5+b5) @ W0 + b0))
// ---------------------------------------------------------------------------
__global__ __launch_bounds__(NTG, 2)
void gemm_user_triple(const float* __restrict__ hu,
                      const __nv_bfloat16* W4h, const __nv_bfloat16* W4l, const float* b4,
                      const float* __restrict__ meanU,
                      const __nv_bfloat16* W5h, const __nv_bfloat16* W5l, const float* b5,
                      const __nv_bfloat16* W0h, const __nv_bfloat16* W0l, const float* b0,
                      float* __restrict__ meanA2)
{
    extern __shared__ char sm[];
    char* pAh = sm;            char* pAl = sm + T64;
    char* pBh = sm + 2 * T64;  char* pBl = pBh + T128;
    const int tid = threadIdx.x;
    const int row0 = blockIdx.x * 64;
    const uint32_t base = smem_u32(sm);

    load_B_sync(W4h, W4l, pBh, pBl, tid, 128);
    load_split_A<0>(hu, nullptr, row0, pAh, pAl, tid);
    __syncthreads();

    const int w = tid >> 5, lane = tid & 31;
    const int m0 = (w >> 1) * 32, n0 = (w & 1) * 64;
    const int rr = lane & 7, quad = lane >> 3;
    const uint32_t a_off = (uint32_t)((m0 + rr + ((quad & 1) << 3)) * ASTR + ((quad & 2) << 3));
    const uint32_t b_off = (uint32_t)((n0 + rr + ((quad >> 1) << 3)) * ASTR + ((quad & 1) << 4));

    float acc[2][8][4];
    zero_acc<2, 8>(acc);
    mma_3p<2, 8>(base, base + T64, base + 2 * T64, base + 2 * T64 + T128, a_off, b_off, acc);
    __syncthreads();
    epi_resplit<2, 8, true, 4>(acc, b4, meanU, pAh, pAl, row0, m0, n0, lane);
    load_B_sync(W5h, W5l, pBh, pBl, tid, 128);
    __syncthreads();
    zero_acc<2, 8>(acc);
    mma_3p<2, 8>(base, base + T64, base + 2 * T64, base + 2 * T64 + T128, a_off, b_off, acc);
    __syncthreads();
    epi_resplit<2, 8, false, 0>(acc, b5, nullptr, pAh, pAl, row0, m0, n0, lane);
    load_B_sync(W0h, W0l, pBh, pBl, tid, 128);
    __syncthreads();
    zero_acc<2, 8>(acc);
    mma_3p<2, 8>(base, base + T64, base + 2 * T64, base + 2 * T64 + T128, a_off, b_off, acc);
    epi_mean16<2, 8>(acc, b0, meanA2, row0, m0, n0, lane);
}

// ---------------------------------------------------------------------------
// final triple (TM=64, grid 256): out = normalize(
//    relu((relu(ha2@W1+b1)+meanA2[g64])@W2+b2) @ W_norm' + b_norm )
// ---------------------------------------------------------------------------
__global__ __launch_bounds__(NTG, 2)
void gemm_final(const float* __restrict__ ha2,
                const __nv_bfloat16* W1h, const __nv_bfloat16* W1l, const float* b1,
                const float* __restrict__ meanA2,
                const __nv_bfloat16* W2h, const __nv_bfloat16* W2l, const float* b2,
                const __nv_bfloat16* W6h, const __nv_bfloat16* W6l, const float* b_norm,
                float* __restrict__ outp)
{
    extern __shared__ char sm[];
    char* pAh = sm;            char* pAl = sm + T64;
    char* pBh = sm + 2 * T64;  char* pBl = pBh + T128;
    const int tid = threadIdx.x;
    const int row0 = blockIdx.x * 64;
    const uint32_t base = smem_u32(sm);

    load_B_sync(W1h, W1l, pBh, pBl, tid, 128);
    load_split_A<0>(ha2, nullptr, row0, pAh, pAl, tid);
    __syncthreads();

    const int w = tid >> 5, lane = tid & 31;
    const int m0 = (w >> 1) * 32, n0 = (w & 1) * 64;
    const int rr = lane & 7, quad = lane >> 3;
    const uint32_t a_off = (uint32_t)((m0 + rr + ((quad & 1) << 3)) * ASTR + ((quad & 2) << 3));
    const uint32_t b_off = (uint32_t)((n0 + rr + ((quad >> 1) << 3)) * ASTR + ((quad & 1) << 4));

    float acc[2][8][4];
    zero_acc<2, 8>(acc);
    mma_3p<2, 8>(base, base + T64, base + 2 * T64, base + 2 * T64 + T128, a_off, b_off, acc);
    __syncthreads();
    epi_resplit<2, 8, true, 6>(acc, b1, meanA2, pAh, pAl, row0, m0, n0, lane);
    load_B_sync(W2h, W2l, pBh, pBl, tid, 128);
    __syncthreads();
    zero_acc<2, 8>(acc);
    mma_3p<2, 8>(base, base + T64, base + 2 * T64, base + 2 * T64 + T128, a_off, b_off, acc);
    __syncthreads();
    epi_resplit<2, 8, false, 0>(acc, b2, nullptr, pAh, pAl, row0, m0, n0, lane);
    load_B_sync(W6h, W6l, pBh, pBl, tid, 64);     // W_norm' (64 rows)
    __syncthreads();

    // GEMM3: cols 0..31 real = interleaved re/im pairs; warp covers 16 cols
    const int n03 = (w & 1) * 16;
    const uint32_t b_off3 = (uint32_t)((n03 + rr + ((quad >> 1) << 3)) * ASTR + ((quad & 1) << 4));
    float acc3[2][2][4];
    zero_acc<2, 2>(acc3);
    mma_3p<2, 2>(base, base + T64, base + 2 * T64, base + 2 * T64 + T128, a_off, b_off3, acc3);

    const int tq = lane & 3, gq = lane >> 2;
    #pragma unroll
    for (int mf = 0; mf < 2; ++mf) {
        const int row = row0 + m0 + mf * 16 + gq;
        #pragma unroll
        for (int nf = 0; nf < 2; ++nf) {
            const int c = n03 + nf * 8 + 2 * tq;     // even; rf = c/2
            const int rf = c >> 1;
            const float br = b_norm[rf], bi = b_norm[rf + NRFc];
            {
                const float re = acc3[mf][nf][0] + br;
                const float im = acc3[mf][nf][1] + bi;
                const float inv = rsqrtf(re * re + im * im);
                float2 o = {re * inv, im * inv};
                *reinterpret_cast<float2*>(&outp[(size_t)row * 32 + c]) = o;
            }
            {
                const float re = acc3[mf][nf][2] + br;
                const float im = acc3[mf][nf][3] + bi;
                const float inv = rsqrtf(re * re + im * im);
                float2 o = {re * inv, im * inv};
                *reinterpret_cast<float2*>(&outp[(size_t)(row + 8) * 32 + c]) = o;
            }
        }
    }
}

// ---------------------------------------------------------------------------
// Host
// ---------------------------------------------------------------------------
extern "C" void kernel_launch(void* const* d_in, const int* in_sizes, int n_in,
                              void* d_out, int out_size)
{
    (void)in_sizes; (void)n_in; (void)out_size;

    const float* user_feat = (const float*)d_in[0];
    const float* noise     = (const float*)d_in[1];
    const float* W_ue     = (const float*)d_in[6],  *b_ue     = (const float*)d_in[7];
    const float* W_t      = (const float*)d_in[8],  *b_t      = (const float*)d_in[9];
    const float* b_aggr_a = (const float*)d_in[11];
    const float* b_self_a = (const float*)d_in[13];
    const float* b_comb_a = (const float*)d_in[15];
    const float* b_aggr_u = (const float*)d_in[17];
    const float* b_self_u = (const float*)d_in[19];
    const float* b_comb_u = (const float*)d_in[21];
    const float* W_norm   = (const float*)d_in[22], *b_norm   = (const float*)d_in[23];
    float* out = (float*)d_out;

    float *hu, *ha2, *meanA, *meanU, *meanA2, *hag;
    __nv_bfloat16 *wth, *wtl;
    cudaGetSymbolAddress((void**)&hu,     g_hu);
    cudaGetSymbolAddress((void**)&ha2,    g_ha2);
    cudaGetSymbolAddress((void**)&meanA,  g_meanA);
    cudaGetSymbolAddress((void**)&meanU,  g_meanU);
    cudaGetSymbolAddress((void**)&meanA2, g_meanA2);
    cudaGetSymbolAddress((void**)&hag,    g_hag);
    cudaGetSymbolAddress((void**)&wth,    g_wt_hi);
    cudaGetSymbolAddress((void**)&wtl,    g_wt_lo);

    constexpr int SM_K1 = 78208;
    cudaFuncSetAttribute((void*)k1_prep_stage1,  cudaFuncAttributeMaxDynamicSharedMemorySize, SM_K1);
    cudaFuncSetAttribute((void*)gemm_aggr16,     cudaFuncAttributeMaxDynamicSharedMemorySize, SM_G);
    cudaFuncSetAttribute((void*)gemm_aggr64,     cudaFuncAttributeMaxDynamicSharedMemorySize, SM_G);
    cudaFuncSetAttribute((void*)gemm_dual_agent, cudaFuncAttributeMaxDynamicSharedMemorySize, SM_G);
    cudaFuncSetAttribute((void*)gemm_user_triple,cudaFuncAttributeMaxDynamicSharedMemorySize, SM_G);
    cudaFuncSetAttribute((void*)gemm_final,      cudaFuncAttributeMaxDynamicSharedMemorySize, SM_G);

    const __nv_bfloat16 *WH0 = wth + 0*16384, *WL0 = wtl + 0*16384;   // aggr_a
    const __nv_bfloat16 *WH1 = wth + 1*16384, *WL1 = wtl + 1*16384;   // self_a
    const __nv_bfloat16 *WH2 = wth + 2*16384, *WL2 = wtl + 2*16384;   // comb_a
    const __nv_bfloat16 *WH3 = wth + 3*16384, *WL3 = wtl + 3*16384;   // aggr_u
    const __nv_bfloat16 *WH4 = wth + 4*16384, *WL4 = wtl + 4*16384;   // self_u
    const __nv_bfloat16 *WH5 = wth + 5*16384, *WL5 = wtl + 5*16384;   // comb_u
    const __nv_bfloat16 *WH6 = wth + 6*16384, *WL6 = wtl + 6*16384;   // W_norm'

    // L1: weight prep + stage1 (grid 39)
    k1_prep_stage1<<<7 + NUSER/128, NTK1, SM_K1>>>(
        (const float*)d_in[10], (const float*)d_in[12], (const float*)d_in[14],
        (const float*)d_in[16], (const float*)d_in[18], (const float*)d_in[20],
        W_norm, wth, wtl,
        user_feat, W_ue, b_ue, W_t, b_t, hu, hag);

    // L2: meanA = mean16(relu(hu @ W_aggr_a + b))            (grid 64)
    gemm_aggr16<<<NUSER/64, NTG, SM_G>>>(hu, WH0, WL0, b_aggr_a, meanA);

    // L3: meanU = mean64(relu((noise+hag) @ W_aggr_u + b))   (grid 256, 2 CTAs/SM)
    gemm_aggr64<<<NAG/64, NTG, SM_G>>>(noise, hag, WH3, WL3, b_aggr_u, meanU);

    // L4: agent dual -> ha2                                   (grid 256)
    gemm_dual_agent<<<NAG/64, NTG, SM_G>>>(noise, hag, WH1, WL1, b_self_a,
                                           meanA, WH2, WL2, b_comb_a, ha2);

    // L5: user triple -> meanA2                               (grid 64)
    gemm_user_triple<<<NUSER/64, NTG, SM_G>>>(hu, WH4, WL4, b_self_u, meanU,
                                              WH5, WL5, b_comb_u,
                                              WH0, WL0, b_aggr_a, meanA2);

    // L6: final triple + normalize -> out                     (grid 256)
    gemm_final<<<NAG/64, NTG, SM_G>>>(ha2, WH1, WL1, b_self_a, meanA2,
                                      WH2, WL2, b_comb_a, WH6, WL6, b_norm, out);
}

// round 9
// speedup vs baseline: 1.2437x; 1.2437x over previous
#include <cuda_runtime.h>
#include <cuda_bf16.h>
#include <cstdint>
#include <cstddef>

// ---------------------------------------------------------------------------
// Problem constants
// ---------------------------------------------------------------------------
namespace {
constexpr int Hc    = 128;
constexpr int NRFc  = 16;
constexpr int NUSER = 4096;
constexpr int NAG   = 16384;
constexpr int APAD  = 136;        // bf16 elems per smem row
constexpr int ASTR  = APAD * 2;   // 272 bytes
constexpr int T64   = 64  * ASTR; // 17408
constexpr int T128  = 128 * ASTR; // 34816
constexpr int NT    = 256;        // GEMM kernel threads (8 warps)
constexpr int NTK1  = 512;
}

// ---------------------------------------------------------------------------
// Scratch (device globals — no allocation allowed)
// ---------------------------------------------------------------------------
__device__ float g_hu    [NUSER * Hc];
__device__ float g_ha2   [NAG   * Hc];
__device__ float g_meanA [256 * Hc];
__device__ float g_meanU [256 * Hc];
__device__ float g_meanA2[256 * Hc];
__device__ float g_hag   [256 * Hc];
// Pre-transposed + hi/lo-split weights: slots 0..5 = HxH, slot 6 = W_norm' (64x128)
__device__ __nv_bfloat16 g_wt_hi[7 * Hc * Hc];
__device__ __nv_bfloat16 g_wt_lo[7 * Hc * Hc];

// ---------------------------------------------------------------------------
// Helpers (R4-identical)
// ---------------------------------------------------------------------------
__device__ __forceinline__ uint32_t smem_u32(const void* p) {
    uint32_t a;
    asm("{ .reg .u64 t; cvta.to.shared.u64 t, %1; cvt.u32.u64 %0, t; }"
        : "=r"(a) : "l"(p));
    return a;
}
__device__ __forceinline__ void ldsm4(uint32_t* r, uint32_t addr) {
    asm volatile("ldmatrix.sync.aligned.m8n8.x4.shared.b16 {%0,%1,%2,%3}, [%4];"
                 : "=r"(r[0]), "=r"(r[1]), "=r"(r[2]), "=r"(r[3]) : "r"(addr));
}
__device__ __forceinline__ void mma16816(float* d, const uint32_t* a, const uint32_t* b) {
    asm volatile(
        "mma.sync.aligned.m16n8k16.row.col.f32.bf16.bf16.f32 "
        "{%0,%1,%2,%3}, {%4,%5,%6,%7}, {%8,%9}, {%0,%1,%2,%3};"
        : "+f"(d[0]), "+f"(d[1]), "+f"(d[2]), "+f"(d[3])
        : "r"(a[0]), "r"(a[1]), "r"(a[2]), "r"(a[3]), "r"(b[0]), "r"(b[1]));
}
__device__ __forceinline__ uint32_t pack_bf2(__nv_bfloat16 a, __nv_bfloat16 b) {
    return (uint32_t)__bfloat16_as_ushort(a) | ((uint32_t)__bfloat16_as_ushort(b) << 16);
}
__device__ __forceinline__ void split2(float a, float b, uint32_t& hi, uint32_t& lo) {
    const __nv_bfloat16 h0 = __float2bfloat16(a), h1 = __float2bfloat16(b);
    hi = pack_bf2(h0, h1);
    lo = pack_bf2(__float2bfloat16(a - __bfloat162float(h0)),
                  __float2bfloat16(b - __bfloat162float(h1)));
}

// serial B tile load (pre-split weights) into padded smem — R4 path
__device__ __forceinline__ void load_B(const __nv_bfloat16* __restrict__ Wh,
                                       const __nv_bfloat16* __restrict__ Wl,
                                       char* pBh, char* pBl, int tid, int rows)
{
    const uint4* wh = reinterpret_cast<const uint4*>(Wh);
    const uint4* wl = reinterpret_cast<const uint4*>(Wl);
    for (int i = tid; i < rows * 16; i += NT) {
        const uint32_t o = (uint32_t)((i >> 4) * ASTR + (i & 15) * 16);
        *reinterpret_cast<uint4*>(pBh + o) = wh[i];
        *reinterpret_cast<uint4*>(pBl + o) = wl[i];
    }
}

// A tile: fp32 load (+optional hag broadcast, group = row>>6), hi/lo split — R4 path
template<int TM, bool ADD>
__device__ __forceinline__ void load_split_A(const float* __restrict__ A,
                                             const float* __restrict__ addv,
                                             int row0, char* pAh, char* pAl, int tid)
{
    #pragma unroll
    for (int i = tid; i < TM * 16; i += NT) {
        const int r = i >> 4, k = (i & 15) * 8;
        const float* ap = A + (size_t)(row0 + r) * Hc + k;
        float v[8];
        *reinterpret_cast<float4*>(&v[0]) = *reinterpret_cast<const float4*>(ap);
        *reinterpret_cast<float4*>(&v[4]) = *reinterpret_cast<const float4*>(ap + 4);
        if (ADD) {
            const float* mp = addv + ((row0 + r) >> 6) * Hc + k;
            float m[8];
            *reinterpret_cast<float4*>(&m[0]) = *reinterpret_cast<const float4*>(mp);
            *reinterpret_cast<float4*>(&m[4]) = *reinterpret_cast<const float4*>(mp + 4);
            #pragma unroll
            for (int j = 0; j < 8; ++j) v[j] += m[j];
        }
        uint32_t hb[4], lb[4];
        #pragma unroll
        for (int j = 0; j < 4; ++j) split2(v[2*j], v[2*j+1], hb[j], lb[j]);
        const uint32_t o = (uint32_t)(r * ASTR + (i & 15) * 16);
        *reinterpret_cast<uint4*>(pAh + o) = *reinterpret_cast<uint4*>(hb);
        *reinterpret_cast<uint4*>(pAl + o) = *reinterpret_cast<uint4*>(lb);
    }
}

// 3-pass hi/lo MMA over K=128 — R4 inner loop, verbatim
template<int MF, int NF>
__device__ __forceinline__ void mma_3p(uint32_t aAh, uint32_t aAl,
                                       uint32_t aBh, uint32_t aBl,
                                       uint32_t a_off, uint32_t b_off,
                                       float (*acc)[NF][4])
{
    #pragma unroll
    for (int pass = 0; pass < 3; ++pass) {
        const uint32_t Ab = (pass == 2 ? aAl : aAh) + a_off;
        const uint32_t Bb = (pass == 1 ? aBl : aBh) + b_off;
        #pragma unroll
        for (int kc = 0; kc < 8; ++kc) {
            const uint32_t kb = (uint32_t)kc * 32;
            uint32_t af[MF][4];
            #pragma unroll
            for (int mf = 0; mf < MF; ++mf)
                ldsm4(af[mf], Ab + (uint32_t)(mf * 16 * ASTR) + kb);
            uint32_t bfr[NF][2];
            #pragma unroll
            for (int p = 0; p < NF / 2; ++p) {
                uint32_t t[4];
                ldsm4(t, Bb + (uint32_t)(p * 16 * ASTR) + kb);
                bfr[2*p][0] = t[0]; bfr[2*p][1] = t[1];
                bfr[2*p+1][0] = t[2]; bfr[2*p+1][1] = t[3];
            }
            #pragma unroll
            for (int mf = 0; mf < MF; ++mf)
                #pragma unroll
                for (int nf = 0; nf < NF; ++nf)
                    mma16816(acc[mf][nf], af[mf], bfr[nf]);
        }
    }
}
template<int MF, int NF>
__device__ __forceinline__ void zero_acc(float (*acc)[NF][4]) {
    #pragma unroll
    for (int mf = 0; mf < MF; ++mf)
        #pragma unroll
        for (int nf = 0; nf < NF; ++nf)
            acc[mf][nf][0] = acc[mf][nf][1] = acc[mf][nf][2] = acc[mf][nf][3] = 0.f;
}

// epilogue: relu(acc+b) (+mean[g]) re-split into A tiles — R4 math
template<int MF, bool ADDMEAN, int SHIFT>
__device__ __forceinline__ void epi_resplit(float (*acc)[4][4],
                                            const float* __restrict__ bias,
                                            const float* __restrict__ meanv,
                                            char* pAh, char* pAl,
                                            int row0, int m0, int n0, int lane)
{
    const int tq = lane & 3, gq = lane >> 2;
    #pragma unroll
    for (int mf = 0; mf < MF; ++mf) {
        const int r0 = m0 + mf * 16 + gq;
        const int g = ADDMEAN ? ((SHIFT == 6) ? ((row0 + m0) >> 6)
                                              : ((row0 + m0 + mf * 16) >> 4)) : 0;
        #pragma unroll
        for (int nf = 0; nf < 4; ++nf) {
            const int c = n0 + nf * 8 + 2 * tq;
            float mx = 0.f, my = 0.f;
            if (ADDMEAN) {
                const float2 mv = *reinterpret_cast<const float2*>(&meanv[g * Hc + c]);
                mx = mv.x; my = mv.y;
            }
            const float bb0 = bias[c], bb1 = bias[c + 1];
            const float e0 = fmaxf(acc[mf][nf][0] + bb0, 0.f) + mx;
            const float e1 = fmaxf(acc[mf][nf][1] + bb1, 0.f) + my;
            const float e2 = fmaxf(acc[mf][nf][2] + bb0, 0.f) + mx;
            const float e3 = fmaxf(acc[mf][nf][3] + bb1, 0.f) + my;
            uint32_t hi0, lo0, hi1, lo1;
            split2(e0, e1, hi0, lo0);
            split2(e2, e3, hi1, lo1);
            *reinterpret_cast<uint32_t*>(pAh + r0 * ASTR + c * 2) = hi0;
            *reinterpret_cast<uint32_t*>(pAl + r0 * ASTR + c * 2) = lo0;
            *reinterpret_cast<uint32_t*>(pAh + (r0 + 8) * ASTR + c * 2) = hi1;
            *reinterpret_cast<uint32_t*>(pAl + (r0 + 8) * ASTR + c * 2) = lo1;
        }
    }
}

// mean-16 epilogue: each 16-row m-frag is one group — R4 math
template<int MF>
__device__ __forceinline__ void epi_mean16(float (*acc)[4][4],
                                           const float* __restrict__ bias,
                                           float* __restrict__ outp,
                                           int row0, int m0, int n0, int lane)
{
    const int tq = lane & 3;
    #pragma unroll
    for (int mf = 0; mf < MF; ++mf) {
        const int grp = (row0 + m0 + mf * 16) >> 4;
        #pragma unroll
        for (int nf = 0; nf < 4; ++nf) {
            const int c = n0 + nf * 8 + 2 * tq;
            const float bb0 = bias[c], bb1 = bias[c + 1];
            float s0 = fmaxf(acc[mf][nf][0] + bb0, 0.f)
                     + fmaxf(acc[mf][nf][2] + bb0, 0.f);
            float s1 = fmaxf(acc[mf][nf][1] + bb1, 0.f)
                     + fmaxf(acc[mf][nf][3] + bb1, 0.f);
            s0 += __shfl_xor_sync(~0u, s0, 4);  s1 += __shfl_xor_sync(~0u, s1, 4);
            s0 += __shfl_xor_sync(~0u, s0, 8);  s1 += __shfl_xor_sync(~0u, s1, 8);
            s0 += __shfl_xor_sync(~0u, s0, 16); s1 += __shfl_xor_sync(~0u, s1, 16);
            if (lane < 4) {
                float2 o2 = {s0 * 0.0625f, s1 * 0.0625f};
                *reinterpret_cast<float2*>(&outp[grp * Hc + n0 + nf * 8 + 2 * lane]) = o2;
            }
        }
    }
}

// ---------------------------------------------------------------------------
// K1: prep (blocks 0..6) + stage1 (blocks 7..38)  [512 threads] — R6-verified
// ---------------------------------------------------------------------------
__global__ __launch_bounds__(NTK1, 1)
void k1_prep_stage1(const float* W0, const float* W1, const float* W2,
                    const float* W3, const float* W4, const float* W5,
                    const float* Wn,
                    __nv_bfloat16* oh, __nv_bfloat16* ol,
                    const float* __restrict__ uf,
                    const float* __restrict__ W_ue, const float* __restrict__ b_ue,
                    const float* __restrict__ W_t,  const float* __restrict__ b_t,
                    float* __restrict__ hu, float* __restrict__ hag)
{
    extern __shared__ char smraw[];
    const int tid = threadIdx.x;

    if (blockIdx.x < 7) {
        float* st = reinterpret_cast<float*>(smraw);
        const int m = blockIdx.x;
        uint32_t* ph = reinterpret_cast<uint32_t*>(oh + (size_t)m * Hc * Hc);
        uint32_t* pl = reinterpret_cast<uint32_t*>(ol + (size_t)m * Hc * Hc);
        if (m < 6) {
            const float* Ws[6] = {W0, W1, W2, W3, W4, W5};
            const float* W = Ws[m];
            for (int i = tid; i < Hc * 32; i += NTK1) {
                const int kr = i >> 5, c4 = i & 31;
                *reinterpret_cast<float4*>(&st[kr * 132 + c4 * 4]) =
                    reinterpret_cast<const float4*>(W)[i];
            }
            __syncthreads();
            for (int i = tid; i < Hc * 64; i += NTK1) {
                const int n = i >> 6, k2 = (i & 63) * 2;
                uint32_t hi, lo;
                split2(st[k2 * 132 + n], st[(k2 + 1) * 132 + n], hi, lo);
                ph[n * 64 + (i & 63)] = hi;
                pl[n * 64 + (i & 63)] = lo;
            }
        } else {
            for (int i = tid; i < Hc * 8; i += NTK1) {
                const int kr = i >> 3, c4 = i & 7;
                *reinterpret_cast<float4*>(&st[kr * 36 + c4 * 4]) =
                    reinterpret_cast<const float4*>(Wn)[i];
            }
            __syncthreads();
            for (int i = tid; i < 64 * 64; i += NTK1) {
                const int rowp = i >> 6, k = (i & 63) * 2;
                uint32_t hi = 0, lo = 0;
                if (rowp < 32) {
                    const int n = (rowp & 1) * 16 + (rowp >> 1);
                    split2(st[k * 36 + n], st[(k + 1) * 36 + n], hi, lo);
                }
                ph[rowp * 64 + (i & 63)] = hi;
                pl[rowp * 64 + (i & 63)] = lo;
            }
        }
        return;
    }

    // ---- stage1 ----
    float* sA    = reinterpret_cast<float*>(smraw);           // [128][36]
    float* sW    = reinterpret_cast<float*>(smraw + 18432);   // [32][128]
    float* spart = reinterpret_cast<float*>(smraw + 65536);   // [16][132]
    float* smean = reinterpret_cast<float*>(smraw + 73984);   // [8][132]
    float* sWt   = reinterpret_cast<float*>(smraw);           // phase2: [128][128]

    const int row0 = (blockIdx.x - 7) * 128;

    for (int i = tid; i < 1024; i += NTK1) {
        const int r = i >> 3, k4 = i & 7;
        *reinterpret_cast<float4*>(&sA[r * 36 + k4 * 4]) =
            reinterpret_cast<const float4*>(uf)[(size_t)row0 * 8 + i];
    }
    for (int i = tid; i < 1024; i += NTK1)
        reinterpret_cast<float4*>(sW)[i] = reinterpret_cast<const float4*>(W_ue)[i];
    __syncthreads();

    {
        const int tx = tid & 31, ty = tid >> 5;
        const float4 b4 = reinterpret_cast<const float4*>(b_ue)[tx];
        float4 msum = {0.f, 0.f, 0.f, 0.f};
        #pragma unroll 2
        for (int i = 0; i < 8; ++i) {
            const int r = ty * 8 + i;
            float4 acc = b4;
            #pragma unroll
            for (int k = 0; k < 32; ++k) {
                const float a = sA[r * 36 + k];
                const float4 w = reinterpret_cast<const float4*>(sW)[k * 32 + tx];
                acc.x += a * w.x; acc.y += a * w.y; acc.z += a * w.z; acc.w += a * w.w;
            }
            acc.x = fmaxf(acc.x, 0.f); acc.y = fmaxf(acc.y, 0.f);
            acc.z = fmaxf(acc.z, 0.f); acc.w = fmaxf(acc.w, 0.f);
            reinterpret_cast<float4*>(hu)[(size_t)(row0 + r) * 32 + tx] = acc;
            msum.x += acc.x; msum.y += acc.y; msum.z += acc.z; msum.w += acc.w;
        }
        *reinterpret_cast<float4*>(&spart[ty * 132 + tx * 4]) = msum;
    }
    __syncthreads();
    for (int i = tid; i < 1024; i += NTK1) {
        const int g = i >> 7, c = i & 127;
        smean[g * 132 + c] = (spart[(2*g) * 132 + c] + spart[(2*g+1) * 132 + c]) * 0.0625f;
    }
    __syncthreads();
    for (int i = tid; i < 4096; i += NTK1)
        reinterpret_cast<float4*>(sWt)[i] = reinterpret_cast<const float4*>(W_t)[i];
    __syncthreads();
    if (tid < 256) {
        const int gr = tid >> 5, col4 = tid & 31;
        float4 acc = reinterpret_cast<const float4*>(b_t)[col4];
        #pragma unroll 4
        for (int k = 0; k < 128; ++k) {
            const float a = smean[gr * 132 + k];
            const float4 w = reinterpret_cast<const float4*>(sWt)[k * 32 + col4];
            acc.x += a * w.x; acc.y += a * w.y; acc.z += a * w.z; acc.w += a * w.w;
        }
        acc.x = fmaxf(acc.x, 0.f); acc.y = fmaxf(acc.y, 0.f);
        acc.z = fmaxf(acc.z, 0.f); acc.w = fmaxf(acc.w, 0.f);
        reinterpret_cast<float4*>(hag)[(size_t)((blockIdx.x - 7) * 8 + gr) * 32 + col4] = acc;
    }
}

// ---------------------------------------------------------------------------
// aggr GEMM -> group mean only (R4's gemm_aggr, verbatim structure)
//  OUTMODE 1: group=16 rows.  OUTMODE 2: group=64 rows (TM=128, WM=64).
// ---------------------------------------------------------------------------
template<int TM, bool ADD, int OUTMODE>
__global__ __launch_bounds__(NT, 1)
void gemm_aggr(const float* __restrict__ A, const float* __restrict__ addv,
               const __nv_bfloat16* __restrict__ Wh, const __nv_bfloat16* __restrict__ Wl,
               const float* __restrict__ bias, float* __restrict__ outp)
{
    extern __shared__ char sm[];
    constexpr int TILEA = TM * ASTR;
    char* pAh = sm;
    char* pAl = sm + TILEA;
    char* pBh = sm + 2 * TILEA;
    char* pBl = pBh + T128;

    const int tid = threadIdx.x;
    const int row0 = blockIdx.x * TM;
    const uint32_t base = smem_u32(sm);

    load_B(Wh, Wl, pBh, pBl, tid, 128);
    load_split_A<TM, ADD>(A, addv, row0, pAh, pAl, tid);
    __syncthreads();

    constexpr int WM = TM / 2, MF = WM / 16;
    const int w = tid >> 5, lane = tid & 31;
    const int m0 = (w >> 2) * WM, n0 = (w & 3) * 32;
    const int rr = lane & 7, quad = lane >> 3;
    const uint32_t a_off = (uint32_t)((m0 + rr + ((quad & 1) << 3)) * ASTR + ((quad & 2) << 3));
    const uint32_t b_off = (uint32_t)((n0 + rr + ((quad >> 1) << 3)) * ASTR + ((quad & 1) << 4));

    float acc[MF][4][4];
    zero_acc<MF, 4>(acc);
    mma_3p<MF, 4>(base, base + TILEA, base + 2 * TILEA, base + 2 * TILEA + T128,
                  a_off, b_off, acc);

    if (OUTMODE == 1) {
        epi_mean16<MF>(acc, bias, outp, row0, m0, n0, lane);
    } else {
        const int tq = lane & 3;
        float s0[4], s1[4];
        #pragma unroll
        for (int nf = 0; nf < 4; ++nf) { s0[nf] = 0.f; s1[nf] = 0.f; }
        #pragma unroll
        for (int mf = 0; mf < MF; ++mf)
            #pragma unroll
            for (int nf = 0; nf < 4; ++nf) {
                const int c = n0 + nf * 8 + 2 * tq;
                const float bb0 = bias[c], bb1 = bias[c + 1];
                s0[nf] += fmaxf(acc[mf][nf][0] + bb0, 0.f)
                        + fmaxf(acc[mf][nf][2] + bb0, 0.f);
                s1[nf] += fmaxf(acc[mf][nf][1] + bb1, 0.f)
                        + fmaxf(acc[mf][nf][3] + bb1, 0.f);
            }
        const int grp = (row0 + m0) >> 6;
        #pragma unroll
        for (int nf = 0; nf < 4; ++nf) {
            float a0 = s0[nf], a1 = s1[nf];
            a0 += __shfl_xor_sync(~0u, a0, 4);  a1 += __shfl_xor_sync(~0u, a1, 4);
            a0 += __shfl_xor_sync(~0u, a0, 8);  a1 += __shfl_xor_sync(~0u, a1, 8);
            a0 += __shfl_xor_sync(~0u, a0, 16); a1 += __shfl_xor_sync(~0u, a1, 16);
            if (lane < 4) {
                float2 o2 = {a0 * (1.f/64.f), a1 * (1.f/64.f)};
                *reinterpret_cast<float2*>(&outp[grp * Hc + n0 + nf * 8 + 2 * lane]) = o2;
            }
        }
    }
}

// ---------------------------------------------------------------------------
// Agent dual (TM=128): ha2 = relu((relu((noise+hag)@W1+b1)+meanA[g64])@W2+b2)
// R4's gemm_dual<128,true,6>, verbatim (serial B reload, no cp.async).
// ---------------------------------------------------------------------------
__global__ __launch_bounds__(NT, 1)
void gemm_dual_agent(const float* __restrict__ noise, const float* __restrict__ hag,
                     const __nv_bfloat16* W1h, const __nv_bfloat16* W1l, const float* b1,
                     const float* __restrict__ meanv,
                     const __nv_bfloat16* W2h, const __nv_bfloat16* W2l, const float* b2,
                     float* __restrict__ outp)
{
    extern __shared__ char sm[];
    char* pAh = sm;
    char* pAl = sm + T128;
    char* pBh = sm + 2 * T128;
    char* pBl = pBh + T128;

    const int tid = threadIdx.x;
    const int row0 = blockIdx.x * 128;
    const uint32_t base = smem_u32(sm);

    load_B(W1h, W1l, pBh, pBl, tid, 128);
    load_split_A<128, true>(noise, hag, row0, pAh, pAl, tid);
    __syncthreads();

    constexpr int MF = 4;
    const int w = tid >> 5, lane = tid & 31;
    const int m0 = (w >> 2) * 64, n0 = (w & 3) * 32;
    const int rr = lane & 7, quad = lane >> 3;
    const uint32_t a_off = (uint32_t)((m0 + rr + ((quad & 1) << 3)) * ASTR + ((quad & 2) << 3));
    const uint32_t b_off = (uint32_t)((n0 + rr + ((quad >> 1) << 3)) * ASTR + ((quad & 1) << 4));

    float acc[MF][4][4];
    zero_acc<MF, 4>(acc);
    mma_3p<MF, 4>(base, base + T128, base + 2 * T128, base + 3 * T128, a_off, b_off, acc);
    __syncthreads();
    epi_resplit<MF, true, 6>(acc, b1, meanv, pAh, pAl, row0, m0, n0, lane);
    load_B(W2h, W2l, pBh, pBl, tid, 128);
    __syncthreads();
    zero_acc<MF, 4>(acc);
    mma_3p<MF, 4>(base, base + T128, base + 2 * T128, base + 3 * T128, a_off, b_off, acc);

    const int tq = lane & 3, gq = lane >> 2;
    #pragma unroll
    for (int mf = 0; mf < MF; ++mf) {
        const int row = row0 + m0 + mf * 16 + gq;
        #pragma unroll
        for (int nf = 0; nf < 4; ++nf) {
            const int c = n0 + nf * 8 + 2 * tq;
            const float bb0 = b2[c], bb1 = b2[c + 1];
            float2 lo = {fmaxf(acc[mf][nf][0] + bb0, 0.f),
                         fmaxf(acc[mf][nf][1] + bb1, 0.f)};
            float2 hi = {fmaxf(acc[mf][nf][2] + bb0, 0.f),
                         fmaxf(acc[mf][nf][3] + bb1, 0.f)};
            *reinterpret_cast<float2*>(&outp[(size_t)row * Hc + c]) = lo;
            *reinterpret_cast<float2*>(&outp[(size_t)(row + 8) * Hc + c]) = hi;
        }
    }
}

// ---------------------------------------------------------------------------
// User triple (TM=64, grid 64): meanA2 = mean16(relu(
//    relu((relu(hu@W4+b4)+meanU[g16])@W5+b5) @ W0 + b0))
// R4's gemm_dual<64,false,4> + third GEMM (same serial pattern).
// ---------------------------------------------------------------------------
__global__ __launch_bounds__(NT, 1)
void gemm_user_triple(const float* __restrict__ hu,
                      const __nv_bfloat16* W4h, const __nv_bfloat16* W4l, const float* b4,
                      const float* __restrict__ meanU,
                      const __nv_bfloat16* W5h, const __nv_bfloat16* W5l, const float* b5,
                      const __nv_bfloat16* W0h, const __nv_bfloat16* W0l, const float* b0,
                      float* __restrict__ meanA2)
{
    extern __shared__ char sm[];
    char* pAh = sm;
    char* pAl = sm + T64;
    char* pBh = sm + 2 * T64;
    char* pBl = pBh + T128;

    const int tid = threadIdx.x;
    const int row0 = blockIdx.x * 64;
    const uint32_t base = smem_u32(sm);

    load_B(W4h, W4l, pBh, pBl, tid, 128);
    load_split_A<64, false>(hu, nullptr, row0, pAh, pAl, tid);
    __syncthreads();

    constexpr int MF = 2;
    const int w = tid >> 5, lane = tid & 31;
    const int m0 = (w >> 2) * 32, n0 = (w & 3) * 32;
    const int rr = lane & 7, quad = lane >> 3;
    const uint32_t a_off = (uint32_t)((m0 + rr + ((quad & 1) << 3)) * ASTR + ((quad & 2) << 3));
    const uint32_t b_off = (uint32_t)((n0 + rr + ((quad >> 1) << 3)) * ASTR + ((quad & 1) << 4));

    float acc[MF][4][4];
    zero_acc<MF, 4>(acc);
    mma_3p<MF, 4>(base, base + T64, base + 2 * T64, base + 2 * T64 + T128, a_off, b_off, acc);
    __syncthreads();
    epi_resplit<MF, true, 4>(acc, b4, meanU, pAh, pAl, row0, m0, n0, lane);
    load_B(W5h, W5l, pBh, pBl, tid, 128);
    __syncthreads();
    zero_acc<MF, 4>(acc);
    mma_3p<MF, 4>(base, base + T64, base + 2 * T64, base + 2 * T64 + T128, a_off, b_off, acc);
    __syncthreads();
    epi_resplit<MF, false, 0>(acc, b5, nullptr, pAh, pAl, row0, m0, n0, lane);
    load_B(W0h, W0l, pBh, pBl, tid, 128);
    __syncthreads();
    zero_acc<MF, 4>(acc);
    mma_3p<MF, 4>(base, base + T64, base + 2 * T64, base + 2 * T64 + T128, a_off, b_off, acc);
    epi_mean16<MF>(acc, b0, meanA2, row0, m0, n0, lane);
}

// ---------------------------------------------------------------------------
// Final triple (TM=128): out = normalize(
//    relu((relu(ha2@W1+b1)+meanA2[g64])@W2+b2) @ W_norm' + b_norm )
// R4's gemm_triple, verbatim.
// ---------------------------------------------------------------------------
__global__ __launch_bounds__(NT, 1)
void gemm_final(const float* __restrict__ ha2,
                const __nv_bfloat16* W1h, const __nv_bfloat16* W1l, const float* b1,
                const float* __restrict__ meanA2,
                const __nv_bfloat16* W2h, const __nv_bfloat16* W2l, const float* b2,
                const __nv_bfloat16* W6h, const __nv_bfloat16* W6l, const float* b_norm,
                float* __restrict__ outp)
{
    extern __shared__ char sm[];
    char* pAh = sm;
    char* pAl = sm + T128;
    char* pBh = sm + 2 * T128;
    char* pBl = pBh + T128;

    const int tid = threadIdx.x;
    const int row0 = blockIdx.x * 128;
    const uint32_t base = smem_u32(sm);

    load_B(W1h, W1l, pBh, pBl, tid, 128);
    load_split_A<128, false>(ha2, nullptr, row0, pAh, pAl, tid);
    __syncthreads();

    constexpr int MF = 4;
    const int w = tid >> 5, lane = tid & 31;
    const int m0 = (w >> 2) * 64, n0 = (w & 3) * 32;
    const int rr = lane & 7, quad = lane >> 3;
    const uint32_t a_off = (uint32_t)((m0 + rr + ((quad & 1) << 3)) * ASTR + ((quad & 2) << 3));
    const uint32_t b_off = (uint32_t)((n0 + rr + ((quad >> 1) << 3)) * ASTR + ((quad & 1) << 4));

    float acc[MF][4][4];
    zero_acc<MF, 4>(acc);
    mma_3p<MF, 4>(base, base + T128, base + 2 * T128, base + 3 * T128, a_off, b_off, acc);
    __syncthreads();
    epi_resplit<MF, true, 6>(acc, b1, meanA2, pAh, pAl, row0, m0, n0, lane);
    load_B(W2h, W2l, pBh, pBl, tid, 128);
    __syncthreads();
    zero_acc<MF, 4>(acc);
    mma_3p<MF, 4>(base, base + T128, base + 2 * T128, base + 3 * T128, a_off, b_off, acc);
    __syncthreads();
    epi_resplit<MF, false, 0>(acc, b2, nullptr, pAh, pAl, row0, m0, n0, lane);
    load_B(W6h, W6l, pBh, pBl, tid, 64);     // W_norm' (64 rows)
    __syncthreads();

    // GEMM3: cols 0..31 real = interleaved re/im pairs; per warp 16 cols
    const int n03 = (w & 3) * 16;
    const uint32_t b_off3 = (uint32_t)((n03 + rr + ((quad >> 1) << 3)) * ASTR + ((quad & 1) << 4));
    float acc3[MF][2][4];
    zero_acc<MF, 2>(acc3);
    mma_3p<MF, 2>(base, base + T128, base + 2 * T128, base + 3 * T128, a_off, b_off3, acc3);

    if ((w & 3) < 2) {
        const int tq = lane & 3, gq = lane >> 2;
        #pragma unroll
        for (int mf = 0; mf < MF; ++mf) {
            const int row = row0 + m0 + mf * 16 + gq;
            #pragma unroll
            for (int nf = 0; nf < 2; ++nf) {
                const int c = n03 + nf * 8 + 2 * tq;   // even; rf = c/2
                const int rf = c >> 1;
                const float br = b_norm[rf], bi = b_norm[rf + NRFc];
                {
                    const float re = acc3[mf][nf][0] + br;
                    const float im = acc3[mf][nf][1] + bi;
                    const float inv = rsqrtf(re * re + im * im);
                    float2 o = {re * inv, im * inv};
                    *reinterpret_cast<float2*>(&outp[(size_t)row * 32 + c]) = o;
                }
                {
                    const float re = acc3[mf][nf][2] + br;
                    const float im = acc3[mf][nf][3] + bi;
                    const float inv = rsqrtf(re * re + im * im);
                    float2 o = {re * inv, im * inv};
                    *reinterpret_cast<float2*>(&outp[(size_t)(row + 8) * 32 + c]) = o;
                }
            }
        }
    }
}

// ---------------------------------------------------------------------------
// Host
// ---------------------------------------------------------------------------
extern "C" void kernel_launch(void* const* d_in, const int* in_sizes, int n_in,
                              void* d_out, int out_size)
{
    (void)in_sizes; (void)n_in; (void)out_size;

    const float* user_feat = (const float*)d_in[0];
    const float* noise     = (const float*)d_in[1];
    const float* W_ue     = (const float*)d_in[6],  *b_ue     = (const float*)d_in[7];
    const float* W_t      = (const float*)d_in[8],  *b_t      = (const float*)d_in[9];
    const float* b_aggr_a = (const float*)d_in[11];
    const float* b_self_a = (const float*)d_in[13];
    const float* b_comb_a = (const float*)d_in[15];
    const float* b_aggr_u = (const float*)d_in[17];
    const float* b_self_u = (const float*)d_in[19];
    const float* b_comb_u = (const float*)d_in[21];
    const float* W_norm   = (const float*)d_in[22], *b_norm   = (const float*)d_in[23];
    float* out = (float*)d_out;

    float *hu, *ha2, *meanA, *meanU, *meanA2, *hag;
    __nv_bfloat16 *wth, *wtl;
    cudaGetSymbolAddress((void**)&hu,     g_hu);
    cudaGetSymbolAddress((void**)&ha2,    g_ha2);
    cudaGetSymbolAddress((void**)&meanA,  g_meanA);
    cudaGetSymbolAddress((void**)&meanU,  g_meanU);
    cudaGetSymbolAddress((void**)&meanA2, g_meanA2);
    cudaGetSymbolAddress((void**)&hag,    g_hag);
    cudaGetSymbolAddress((void**)&wth,    g_wt_hi);
    cudaGetSymbolAddress((void**)&wtl,    g_wt_lo);

    constexpr int SM_K1   = 78208;
    constexpr int SM_T64  = 2 * T64  + 2 * T128;   // 104448
    constexpr int SM_T128 = 4 * T128;              // 139264

    cudaFuncSetAttribute((void*)k1_prep_stage1,     cudaFuncAttributeMaxDynamicSharedMemorySize, SM_K1);
    cudaFuncSetAttribute((void*)gemm_aggr<64,false,1>,  cudaFuncAttributeMaxDynamicSharedMemorySize, SM_T64);
    cudaFuncSetAttribute((void*)gemm_aggr<128,true,2>,  cudaFuncAttributeMaxDynamicSharedMemorySize, SM_T128);
    cudaFuncSetAttribute((void*)gemm_dual_agent,    cudaFuncAttributeMaxDynamicSharedMemorySize, SM_T128);
    cudaFuncSetAttribute((void*)gemm_user_triple,   cudaFuncAttributeMaxDynamicSharedMemorySize, SM_T64);
    cudaFuncSetAttribute((void*)gemm_final,         cudaFuncAttributeMaxDynamicSharedMemorySize, SM_T128);

    const __nv_bfloat16 *WH0 = wth + 0*16384, *WL0 = wtl + 0*16384;   // aggr_a
    const __nv_bfloat16 *WH1 = wth + 1*16384, *WL1 = wtl + 1*16384;   // self_a
    const __nv_bfloat16 *WH2 = wth + 2*16384, *WL2 = wtl + 2*16384;   // comb_a
    const __nv_bfloat16 *WH3 = wth + 3*16384, *WL3 = wtl + 3*16384;   // aggr_u
    const __nv_bfloat16 *WH4 = wth + 4*16384, *WL4 = wtl + 4*16384;   // self_u
    const __nv_bfloat16 *WH5 = wth + 5*16384, *WL5 = wtl + 5*16384;   // comb_u
    const __nv_bfloat16 *WH6 = wth + 6*16384, *WL6 = wtl + 6*16384;   // W_norm'

    // L1: weight prep + stage1 (grid 39)
    k1_prep_stage1<<<7 + NUSER/128, NTK1, SM_K1>>>(
        (const float*)d_in[10], (const float*)d_in[12], (const float*)d_in[14],
        (const float*)d_in[16], (const float*)d_in[18], (const float*)d_in[20],
        W_norm, wth, wtl,
        user_feat, W_ue, b_ue, W_t, b_t, hu, hag);

    // L2: meanA = mean16(relu(hu @ W_aggr_a + b))            (grid 64)
    gemm_aggr<64,false,1><<<NUSER/64, NT, SM_T64>>>(hu, nullptr, WH0, WL0, b_aggr_a, meanA);

    // L3: meanU = mean64(relu((noise+hag) @ W_aggr_u + b))   (grid 128)
    gemm_aggr<128,true,2><<<NAG/128, NT, SM_T128>>>(noise, hag, WH3, WL3, b_aggr_u, meanU);

    // L4: agent dual -> ha2                                   (grid 128)
    gemm_dual_agent<<<NAG/128, NT, SM_T128>>>(noise, hag, WH1, WL1, b_self_a,
                                              meanA, WH2, WL2, b_comb_a, ha2);

    // L5: user triple -> meanA2                               (grid 64)
    gemm_user_triple<<<NUSER/64, NT, SM_T64>>>(hu, WH4, WL4, b_self_u, meanU,
                                               WH5, WL5, b_comb_u,
                                               WH0, WL0, b_aggr_a, meanA2);

    // L6: final triple + normalize -> out                     (grid 128)
    gemm_final<<<NAG/128, NT, SM_T128>>>(ha2, WH1, WL1, b_self_a, meanA2,
                                         WH2, WL2, b_comb_a, WH6, WL6, b_norm, out);
}